// round 12
// baseline (speedup 1.0000x reference)
#include <cuda_runtime.h>
#include <math.h>

#define NSEL 1024
#define DD 32
#define KK 128
#define EPSF 1e-5f
#define PI_HALF_F 1.57079632679489661923f

#define TILE 32
#define NTB  (NSEL / TILE)            // 32 tiles per side
#define NBLK (NTB * (NTB + 1) / 2)    // 528 triangular blocks
#define NTHR 256
#define LHS4 36   // padded row stride for L/H tiles (32 + 4) -> 16B aligned
#define WS4  132  // padded row stride for omega tiles (128 + 4) -> 16B aligned

typedef unsigned long long u64;

__device__ __forceinline__ u64 fma2(u64 a, u64 b, u64 c) {
    u64 d;
    asm("fma.rn.f32x2 %0, %1, %2, %3;" : "=l"(d) : "l"(a), "l"(b), "l"(c));
    return d;
}
__device__ __forceinline__ float hsum2(u64 p) {
    float lo, hi;
    asm("mov.b64 {%0, %1}, %2;" : "=f"(lo), "=f"(hi) : "l"(p));
    return lo + hi;
}

// ---- global accumulators (zero-initialized at module load; reset each call) ----
__device__ double g_acc[6];     // 0:S_dd 1:S_oo 2:S_do 3:overlap 4:exceed 5:shape
__device__ unsigned g_count;

// ---------------------------------------------------------------------------
// 528 triangular 32x32 pair tiles, 256 threads, 2x2 microtile. 3 blocks/SM
// (reg-capped via launch_bounds) -> 6 warps/SMSP for latency hiding.
// Diagonal blocks also do exceed+shape; last block finalizes.
__global__ void __launch_bounds__(NTHR, 3)
pair_kernel(const float* __restrict__ cl, const float* __restrict__ ch,
            const float* __restrict__ pL, const float* __restrict__ pH,
            const float* __restrict__ pR, const float* __restrict__ lr,
            const float* __restrict__ om, const int* __restrict__ idxs,
            float* __restrict__ out) {
    extern __shared__ float sm[];
    float* sLi = sm;
    float* sHi = sLi + TILE * LHS4;
    float* sLj = sHi + TILE * LHS4;
    float* sHj = sLj + TILE * LHS4;
    float* sWi = sHj + TILE * LHS4;
    float* sWj = sWi + TILE * WS4;
    __shared__ float sIpI[TILE], sIpJ[TILE];
    __shared__ float bred[6][8];

    int tx = threadIdx.x, ty = threadIdx.y;      // (16, 16)
    int tid = ty * 16 + tx;

    // decode triangular block index -> (by, bx) with by <= bx
    int t = blockIdx.x;
    int by = 0;
    while (t >= NTB - by) { t -= NTB - by; by++; }
    int bx = by + t;
    int i0 = by * TILE;
    int j0 = bx * TILE;
    bool diag = (by == bx);

    // ---- gather L/H tiles (float4 row-chunks): 256 slots, 1 per thread ----
    {
        int r = tid >> 3, dq = tid & 7;
        int gi = idxs[i0 + r];
        int gj = idxs[j0 + r];
        ((float4*)&sLi[r * LHS4])[dq] = ((const float4*)cl)[gi * 8 + dq];
        ((float4*)&sHi[r * LHS4])[dq] = ((const float4*)ch)[gi * 8 + dq];
        ((float4*)&sLj[r * LHS4])[dq] = ((const float4*)cl)[gj * 8 + dq];
        ((float4*)&sHj[r * LHS4])[dq] = ((const float4*)ch)[gj * 8 + dq];
    }
    // ---- omega tiles (coalesced float4): 1024 slots, 4 per thread ----
#pragma unroll
    for (int p = tid; p < TILE * (KK / 4); p += NTHR) {
        int r = p >> 5, kq = p & 31;
        ((float4*)&sWi[r * WS4])[kq] = ((const float4*)om)[(i0 + r) * 32 + kq];
        ((float4*)&sWj[r * WS4])[kq] = ((const float4*)om)[(j0 + r) * 32 + kq];
    }
    __syncthreads();

    // ---- per-row ip = sum(w*w): 8 threads per row, 16 floats each ----
    {
        int row = tid >> 3, q = tid & 7;
        const float4* wi = (const float4*)&sWi[row * WS4 + q * 16];
        const float4* wj = (const float4*)&sWj[row * WS4 + q * 16];
        float pi = 0.f, pj = 0.f;
#pragma unroll
        for (int k = 0; k < 4; k++) {
            float4 a = wi[k], b = wj[k];
            pi = fmaf(a.x, a.x, fmaf(a.y, a.y, fmaf(a.z, a.z, fmaf(a.w, a.w, pi))));
            pj = fmaf(b.x, b.x, fmaf(b.y, b.y, fmaf(b.z, b.z, fmaf(b.w, b.w, pj))));
        }
#pragma unroll
        for (int off = 1; off < 8; off <<= 1) {
            pi += __shfl_xor_sync(0xffffffffu, pi, off);
            pj += __shfl_xor_sync(0xffffffffu, pj, off);
        }
        if (q == 0) { sIpI[row] = pi; sIpJ[row] = pj; }
    }

    // ---- exceed + shape: diagonal blocks only, 4 slots per thread ----
    float exc = 0.f, shp = 0.f;
    if (diag) {
#pragma unroll
        for (int p = tid; p < TILE * DD; p += NTHR) {
            int r = p >> 5, d = p & 31;
            float L = sLi[r * LHS4 + d];
            float H = sHi[r * LHS4 + d];
            float pl = pL[d], ph = pH[d];
            exc += fmaxf(pl - L, 0.f) + fmaxf(H - ph, 0.f)
                 + fmaxf(pl - H, 0.f) + fmaxf(L - ph, 0.f);
            float num = fmaxf((H - L) / pR[d], EPSF);
            float sdiv = num / lr[idxs[i0 + r]];
            sdiv = fminf(fmaxf(sdiv, 0.01f), 1.99f);
            shp += fabsf(tanf((sdiv - 1.0f) * PI_HALF_F));
        }
    }
    __syncthreads();

    // microtile: i-rows {ty, ty+16}, j-cols {tx, tx+16}
    const float* wiB0 = &sWi[ty * WS4];
    const float* wiB1 = &sWi[(ty + 16) * WS4];
    const float* wjB0 = &sWj[tx * WS4];
    const float* wjB1 = &sWj[(tx + 16) * WS4];

    // ---- embedding dot products: packed f32x2 FMAs ----
    u64 dp[2][2] = {{0ull, 0ull}, {0ull, 0ull}};
#pragma unroll 8
    for (int k = 0; k < KK; k += 4) {
        ulonglong2 a0 = *(const ulonglong2*)(wiB0 + k);
        ulonglong2 a1 = *(const ulonglong2*)(wiB1 + k);
        ulonglong2 b0 = *(const ulonglong2*)(wjB0 + k);
        ulonglong2 b1 = *(const ulonglong2*)(wjB1 + k);
        dp[0][0] = fma2(a0.x, b0.x, dp[0][0]);
        dp[0][1] = fma2(a0.x, b1.x, dp[0][1]);
        dp[1][0] = fma2(a1.x, b0.x, dp[1][0]);
        dp[1][1] = fma2(a1.x, b1.x, dp[1][1]);
        dp[0][0] = fma2(a0.y, b0.y, dp[0][0]);
        dp[0][1] = fma2(a0.y, b1.y, dp[0][1]);
        dp[1][0] = fma2(a1.y, b0.y, dp[1][0]);
        dp[1][1] = fma2(a1.y, b1.y, dp[1][1]);
    }
    float dot[2][2];
#pragma unroll
    for (int r = 0; r < 2; r++)
#pragma unroll
        for (int c = 0; c < 2; c++) dot[r][c] = hsum2(dp[r][c]);

    // ---- box overlap + center distances (d-chunks of 4) ----
    const float* pLi0 = &sLi[ty * LHS4];
    const float* pLi1 = &sLi[(ty + 16) * LHS4];
    const float* pHi0 = &sHi[ty * LHS4];
    const float* pHi1 = &sHi[(ty + 16) * LHS4];
    const float* pLj0 = &sLj[tx * LHS4];
    const float* pLj1 = &sLj[(tx + 16) * LHS4];
    const float* pHj0 = &sHj[tx * LHS4];
    const float* pHj1 = &sHj[(tx + 16) * LHS4];

    float dacc[2][2] = {{0.f, 0.f}, {0.f, 0.f}};
    float ovacc[2][2] = {{0.f, 0.f}, {0.f, 0.f}};

#pragma unroll 2
    for (int d = 0; d < DD; d += 4) {
        float4 Li[2], Hi[2], Si[2], Lj[2], Hj[2], Sj[2];
        Li[0] = *(const float4*)(pLi0 + d); Hi[0] = *(const float4*)(pHi0 + d);
        Li[1] = *(const float4*)(pLi1 + d); Hi[1] = *(const float4*)(pHi1 + d);
        Lj[0] = *(const float4*)(pLj0 + d); Hj[0] = *(const float4*)(pHj0 + d);
        Lj[1] = *(const float4*)(pLj1 + d); Hj[1] = *(const float4*)(pHj1 + d);
#pragma unroll
        for (int r = 0; r < 2; r++) {
            Si[r].x = Li[r].x + Hi[r].x; Si[r].y = Li[r].y + Hi[r].y;
            Si[r].z = Li[r].z + Hi[r].z; Si[r].w = Li[r].w + Hi[r].w;
        }
#pragma unroll
        for (int c = 0; c < 2; c++) {
            Sj[c].x = Lj[c].x + Hj[c].x; Sj[c].y = Lj[c].y + Hj[c].y;
            Sj[c].z = Lj[c].z + Hj[c].z; Sj[c].w = Lj[c].w + Hj[c].w;
        }
#pragma unroll
        for (int r = 0; r < 2; r++)
#pragma unroll
            for (int c = 0; c < 2; c++) {
                float u;
                ovacc[r][c] += fmaxf(fminf(Hi[r].x, Hj[c].x) - fmaxf(Li[r].x, Lj[c].x), 0.f);
                u = Si[r].x - Sj[c].x; dacc[r][c] = fmaf(u, u, dacc[r][c]);
                ovacc[r][c] += fmaxf(fminf(Hi[r].y, Hj[c].y) - fmaxf(Li[r].y, Lj[c].y), 0.f);
                u = Si[r].y - Sj[c].y; dacc[r][c] = fmaf(u, u, dacc[r][c]);
                ovacc[r][c] += fmaxf(fminf(Hi[r].z, Hj[c].z) - fmaxf(Li[r].z, Lj[c].z), 0.f);
                u = Si[r].z - Sj[c].z; dacc[r][c] = fmaf(u, u, dacc[r][c]);
                ovacc[r][c] += fmaxf(fminf(Hi[r].w, Hj[c].w) - fmaxf(Li[r].w, Lj[c].w), 0.f);
                u = Si[r].w - Sj[c].w; dacc[r][c] = fmaf(u, u, dacc[r][c]);
            }
    }

    // ---- combine microtile into scalar partials ----
    float ipi[2], ipj[2];
    ipi[0] = sIpI[ty]; ipi[1] = sIpI[ty + 16];
    ipj[0] = sIpJ[tx]; ipj[1] = sIpJ[tx + 16];

    float s_dd = 0.f, s_oo = 0.f, s_do = 0.f, s_ov = 0.f;
#pragma unroll
    for (int r = 0; r < 2; r++)
#pragma unroll
        for (int c = 0; c < 2; c++) {
            float d2v = 0.25f * dacc[r][c];
            float oDv = fmaxf(fmaf(-2.f, dot[r][c], ipi[r] + ipj[c]), EPSF);
            s_dd = fmaf(d2v, d2v, s_dd);
            s_oo = fmaf(oDv, oDv, s_oo);
            s_do = fmaf(d2v, oDv, s_do);
            if ((i0 + ty + 16 * r) != (j0 + tx + 16 * c))
                s_ov += ovacc[r][c];
        }

    // ---- block reduction ----
#pragma unroll
    for (int off = 16; off > 0; off >>= 1) {
        s_dd += __shfl_xor_sync(0xffffffffu, s_dd, off);
        s_oo += __shfl_xor_sync(0xffffffffu, s_oo, off);
        s_do += __shfl_xor_sync(0xffffffffu, s_do, off);
        s_ov += __shfl_xor_sync(0xffffffffu, s_ov, off);
        exc  += __shfl_xor_sync(0xffffffffu, exc,  off);
        shp  += __shfl_xor_sync(0xffffffffu, shp,  off);
    }
    int warp = tid >> 5, lane = tid & 31;
    if (lane == 0) {
        bred[0][warp] = s_dd; bred[1][warp] = s_oo; bred[2][warp] = s_do;
        bred[3][warp] = s_ov; bred[4][warp] = exc;  bred[5][warp] = shp;
    }
    __syncthreads();
    if (tid == 0) {
        float a0 = 0.f, a1 = 0.f, a2 = 0.f, a3 = 0.f, a4 = 0.f, a5 = 0.f;
#pragma unroll
        for (int w = 0; w < 8; w++) {
            a0 += bred[0][w]; a1 += bred[1][w]; a2 += bred[2][w];
            a3 += bred[3][w]; a4 += bred[4][w]; a5 += bred[5][w];
        }
        double wgt = diag ? 1.0 : 2.0;   // symmetry: off-diagonal tiles count twice
        atomicAdd(&g_acc[0], wgt * (double)a0);
        atomicAdd(&g_acc[1], wgt * (double)a1);
        atomicAdd(&g_acc[2], wgt * (double)a2);
        atomicAdd(&g_acc[3], wgt * (double)a3);
        if (diag) {
            atomicAdd(&g_acc[4], (double)a4);
            atomicAdd(&g_acc[5], (double)a5);
        }

        __threadfence();
        unsigned prev = atomicAdd(&g_count, 1u);
        if (prev == NBLK - 1) {
            __threadfence();
            double S_dd = g_acc[0], S_oo = g_acc[1], S_do = g_acc[2];
            double a = sqrt(S_dd), b = sqrt(S_oo);
            double ac = fmax(a, 1e-5), bc = fmax(b, 1e-5);
            double q = S_dd / (ac * ac) + S_oo / (bc * bc) - 2.0 * S_do / (ac * bc);
            if (q < 0.0) q = 0.0;
            out[0] = (float)(sqrt(q) + g_acc[3] + g_acc[4] + g_acc[5]);
            // reset state for the next graph replay
            g_acc[0] = 0.0; g_acc[1] = 0.0; g_acc[2] = 0.0;
            g_acc[3] = 0.0; g_acc[4] = 0.0; g_acc[5] = 0.0;
            g_count = 0u;
        }
    }
}

// ---------------------------------------------------------------------------
extern "C" void kernel_launch(void* const* d_in, const int* in_sizes, int n_in,
                              void* d_out, int out_size) {
    const float* cl  = (const float*)d_in[0];  // childrenLower  [4096,32]
    const float* ch  = (const float*)d_in[1];  // childrenHigher [4096,32]
    const float* pL  = (const float*)d_in[2];  // parentL_ [32]
    const float* pH  = (const float*)d_in[3];  // parentH_ [32]
    const float* pR  = (const float*)d_in[4];  // parentRange [32]
    const float* lr  = (const float*)d_in[5];  // leavesRatio [4096]
    const float* om  = (const float*)d_in[6];  // omegaEmb [1024,128]
    const int*  idxs = (const int*)d_in[7];    // idIndexes [1024]
    float* out = (float*)d_out;

    const int SMEM = (4 * TILE * LHS4 + 2 * TILE * WS4) * (int)sizeof(float); // 52224 B
    cudaFuncSetAttribute(pair_kernel, cudaFuncAttributeMaxDynamicSharedMemorySize, SMEM);

    pair_kernel<<<NBLK, dim3(16, 16), SMEM>>>(cl, ch, pL, pH, pR, lr, om, idxs, out);
}

// round 13
// speedup vs baseline: 1.1635x; 1.1635x over previous
#include <cuda_runtime.h>
#include <math.h>

#define NSEL 1024
#define DD 32
#define KK 128
#define EPSF 1e-5f
#define PI_HALF_F 1.57079632679489661923f

#define TILE 64
#define NTB  (NSEL / TILE)            // 16 tiles per side
#define NBLK (NTB * (NTB + 1) / 2)    // 136 triangular blocks (one wave)
#define NTHR 512
#define LHS4 36   // padded row stride for L/H/M tiles (32 + 4) -> 16B aligned
#define WS4  132  // padded row stride for omega tiles (128 + 4) -> 16B aligned

typedef unsigned long long u64;

__device__ __forceinline__ u64 fma2(u64 a, u64 b, u64 c) {
    u64 d;
    asm("fma.rn.f32x2 %0, %1, %2, %3;" : "=l"(d) : "l"(a), "l"(b), "l"(c));
    return d;
}
__device__ __forceinline__ float hsum2(u64 p) {
    float lo, hi;
    asm("mov.b64 {%0, %1}, %2;" : "=f"(lo), "=f"(hi) : "l"(p));
    return lo + hi;
}

// ---- global accumulators (zero-initialized at module load; reset each call) ----
__device__ double g_acc[6];     // 0:S_dd 1:S_oo 2:S_do 3:overlap 4:exceed 5:shape
__device__ unsigned g_count;

// ---------------------------------------------------------------------------
// 136 triangular 64x64 pair tiles, 512 threads (16x32), 2x4 microtile.
// d2 computed via ||mi||^2+||mj||^2-2 mi.mj (norm trick) so the box loop is
// overlap-only; both dot products use packed f32x2 FMAs.
__global__ void __launch_bounds__(NTHR)
pair_kernel(const float* __restrict__ cl, const float* __restrict__ ch,
            const float* __restrict__ pL, const float* __restrict__ pH,
            const float* __restrict__ pR, const float* __restrict__ lr,
            const float* __restrict__ om, const int* __restrict__ idxs,
            float* __restrict__ out) {
    extern __shared__ float sm[];
    float* sLi = sm;
    float* sHi = sLi + TILE * LHS4;
    float* sLj = sHi + TILE * LHS4;
    float* sHj = sLj + TILE * LHS4;
    float* sMi = sHj + TILE * LHS4;
    float* sMj = sMi + TILE * LHS4;
    float* sWi = sMj + TILE * LHS4;
    float* sWj = sWi + TILE * WS4;
    __shared__ float sIpI[TILE], sIpJ[TILE];   // ||omega||^2 per row
    __shared__ float sRmI[TILE], sRmJ[TILE];   // ||mid||^2 per row
    __shared__ float bred[6][16];

    int tx = threadIdx.x, ty = threadIdx.y;      // (16, 32)
    int tid = ty * 16 + tx;

    // decode triangular block index -> (by, bx) with by <= bx
    int t = blockIdx.x;
    int by = 0;
    while (t >= NTB - by) { t -= NTB - by; by++; }
    int bx = by + t;
    int i0 = by * TILE;
    int j0 = bx * TILE;
    bool diag = (by == bx);

    // ---- gather L/H tiles + compute mid tiles (one float4 slot/thread) ----
    {
        int r = tid >> 3, dq = tid & 7;
        int gi = idxs[i0 + r];
        int gj = idxs[j0 + r];
        float4 Lf = ((const float4*)cl)[gi * 8 + dq];
        float4 Hf = ((const float4*)ch)[gi * 8 + dq];
        ((float4*)&sLi[r * LHS4])[dq] = Lf;
        ((float4*)&sHi[r * LHS4])[dq] = Hf;
        float4 Mf;
        Mf.x = 0.5f * (Lf.x + Hf.x); Mf.y = 0.5f * (Lf.y + Hf.y);
        Mf.z = 0.5f * (Lf.z + Hf.z); Mf.w = 0.5f * (Lf.w + Hf.w);
        ((float4*)&sMi[r * LHS4])[dq] = Mf;

        Lf = ((const float4*)cl)[gj * 8 + dq];
        Hf = ((const float4*)ch)[gj * 8 + dq];
        ((float4*)&sLj[r * LHS4])[dq] = Lf;
        ((float4*)&sHj[r * LHS4])[dq] = Hf;
        Mf.x = 0.5f * (Lf.x + Hf.x); Mf.y = 0.5f * (Lf.y + Hf.y);
        Mf.z = 0.5f * (Lf.z + Hf.z); Mf.w = 0.5f * (Lf.w + Hf.w);
        ((float4*)&sMj[r * LHS4])[dq] = Mf;
    }
    // ---- omega tiles (coalesced float4) ----
#pragma unroll
    for (int p = tid; p < TILE * (KK / 4); p += NTHR) {    // 2048 slots
        int r = p >> 5, kq = p & 31;
        ((float4*)&sWi[r * WS4])[kq] = ((const float4*)om)[(i0 + r) * 32 + kq];
        ((float4*)&sWj[r * WS4])[kq] = ((const float4*)om)[(j0 + r) * 32 + kq];
    }
    __syncthreads();

    // ---- per-row ||omega||^2 and ||mid||^2 : 8 threads per row ----
    {
        int row = tid >> 3, q = tid & 7;
        const float4* wi = (const float4*)&sWi[row * WS4 + q * 16];
        const float4* wj = (const float4*)&sWj[row * WS4 + q * 16];
        float pi = 0.f, pj = 0.f;
#pragma unroll
        for (int k = 0; k < 4; k++) {
            float4 a = wi[k], b = wj[k];
            pi = fmaf(a.x, a.x, fmaf(a.y, a.y, fmaf(a.z, a.z, fmaf(a.w, a.w, pi))));
            pj = fmaf(b.x, b.x, fmaf(b.y, b.y, fmaf(b.z, b.z, fmaf(b.w, b.w, pj))));
        }
        float4 a = ((const float4*)&sMi[row * LHS4])[q & 7];
        float4 b = ((const float4*)&sMj[row * LHS4])[q & 7];
        float mi2 = fmaf(a.x, a.x, fmaf(a.y, a.y, fmaf(a.z, a.z, a.w * a.w)));
        float mj2 = fmaf(b.x, b.x, fmaf(b.y, b.y, fmaf(b.z, b.z, b.w * b.w)));
#pragma unroll
        for (int off = 1; off < 8; off <<= 1) {
            pi  += __shfl_xor_sync(0xffffffffu, pi,  off);
            pj  += __shfl_xor_sync(0xffffffffu, pj,  off);
            mi2 += __shfl_xor_sync(0xffffffffu, mi2, off);
            mj2 += __shfl_xor_sync(0xffffffffu, mj2, off);
        }
        if (q == 0) { sIpI[row] = pi; sIpJ[row] = pj; sRmI[row] = mi2; sRmJ[row] = mj2; }
    }

    // ---- exceed + shape: diagonal blocks only ----
    float exc = 0.f, shp = 0.f;
    if (diag) {
#pragma unroll
        for (int p = tid; p < TILE * DD; p += NTHR) {
            int r = p >> 5, d = p & 31;
            float L = sLi[r * LHS4 + d];
            float H = sHi[r * LHS4 + d];
            float pl = pL[d], ph = pH[d];
            exc += fmaxf(pl - L, 0.f) + fmaxf(H - ph, 0.f)
                 + fmaxf(pl - H, 0.f) + fmaxf(L - ph, 0.f);
            float num = fmaxf((H - L) / pR[d], EPSF);
            float sdiv = num / lr[idxs[i0 + r]];
            sdiv = fminf(fmaxf(sdiv, 0.01f), 1.99f);
            shp += fabsf(tanf((sdiv - 1.0f) * PI_HALF_F));
        }
    }
    __syncthreads();

    // microtile: i-rows {ty, ty+32}, j-cols {tx + 16c, c<4}
    const float* wiB0 = &sWi[ty * WS4];
    const float* wiB1 = &sWi[(ty + 32) * WS4];
    const float* wjB[4] = { &sWj[tx * WS4], &sWj[(tx + 16) * WS4],
                            &sWj[(tx + 32) * WS4], &sWj[(tx + 48) * WS4] };

    // ---- omega dot products: packed f32x2 FMAs ----
    float dot[2][4];
    {
        u64 dp[2][4] = {{0,0,0,0},{0,0,0,0}};
#pragma unroll 4
        for (int k = 0; k < KK; k += 4) {
            ulonglong2 a0 = *(const ulonglong2*)(wiB0 + k);
            ulonglong2 a1 = *(const ulonglong2*)(wiB1 + k);
#pragma unroll
            for (int c = 0; c < 4; c++) {
                ulonglong2 b = *(const ulonglong2*)(wjB[c] + k);
                dp[0][c] = fma2(a0.x, b.x, dp[0][c]);
                dp[1][c] = fma2(a1.x, b.x, dp[1][c]);
                dp[0][c] = fma2(a0.y, b.y, dp[0][c]);
                dp[1][c] = fma2(a1.y, b.y, dp[1][c]);
            }
        }
#pragma unroll
        for (int r = 0; r < 2; r++)
#pragma unroll
            for (int c = 0; c < 4; c++) dot[r][c] = hsum2(dp[r][c]);
    }

    // ---- mid dot products (d=32): packed f32x2 FMAs ----
    float md[2][4];
    {
        const float* miB0 = &sMi[ty * LHS4];
        const float* miB1 = &sMi[(ty + 32) * LHS4];
        const float* mjB[4] = { &sMj[tx * LHS4], &sMj[(tx + 16) * LHS4],
                                &sMj[(tx + 32) * LHS4], &sMj[(tx + 48) * LHS4] };
        u64 dp[2][4] = {{0,0,0,0},{0,0,0,0}};
#pragma unroll
        for (int k = 0; k < DD; k += 4) {
            ulonglong2 a0 = *(const ulonglong2*)(miB0 + k);
            ulonglong2 a1 = *(const ulonglong2*)(miB1 + k);
#pragma unroll
            for (int c = 0; c < 4; c++) {
                ulonglong2 b = *(const ulonglong2*)(mjB[c] + k);
                dp[0][c] = fma2(a0.x, b.x, dp[0][c]);
                dp[1][c] = fma2(a1.x, b.x, dp[1][c]);
                dp[0][c] = fma2(a0.y, b.y, dp[0][c]);
                dp[1][c] = fma2(a1.y, b.y, dp[1][c]);
            }
        }
#pragma unroll
        for (int r = 0; r < 2; r++)
#pragma unroll
            for (int c = 0; c < 4; c++) md[r][c] = hsum2(dp[r][c]);
    }

    // ---- overlap-only box loop (d-chunks of 4) ----
    float ovacc[2][4] = {{0.f,0.f,0.f,0.f},{0.f,0.f,0.f,0.f}};
#pragma unroll 2
    for (int d = 0; d < DD; d += 4) {
        float4 Li[2], Hi[2], Lj[4], Hj[4];
#pragma unroll
        for (int r = 0; r < 2; r++) {
            Li[r] = *(const float4*)&sLi[(ty + 32 * r) * LHS4 + d];
            Hi[r] = *(const float4*)&sHi[(ty + 32 * r) * LHS4 + d];
        }
#pragma unroll
        for (int c = 0; c < 4; c++) {
            Lj[c] = *(const float4*)&sLj[(tx + 16 * c) * LHS4 + d];
            Hj[c] = *(const float4*)&sHj[(tx + 16 * c) * LHS4 + d];
        }
#pragma unroll
        for (int r = 0; r < 2; r++)
#pragma unroll
            for (int c = 0; c < 4; c++) {
                ovacc[r][c] += fmaxf(fminf(Hi[r].x, Hj[c].x) - fmaxf(Li[r].x, Lj[c].x), 0.f);
                ovacc[r][c] += fmaxf(fminf(Hi[r].y, Hj[c].y) - fmaxf(Li[r].y, Lj[c].y), 0.f);
                ovacc[r][c] += fmaxf(fminf(Hi[r].z, Hj[c].z) - fmaxf(Li[r].z, Lj[c].z), 0.f);
                ovacc[r][c] += fmaxf(fminf(Hi[r].w, Hj[c].w) - fmaxf(Li[r].w, Lj[c].w), 0.f);
            }
    }

    // ---- combine microtile into scalar partials ----
    float ipi[2], ipj[4], rmi[2], rmj[4];
#pragma unroll
    for (int r = 0; r < 2; r++) { ipi[r] = sIpI[ty + 32 * r]; rmi[r] = sRmI[ty + 32 * r]; }
#pragma unroll
    for (int c = 0; c < 4; c++) { ipj[c] = sIpJ[tx + 16 * c]; rmj[c] = sRmJ[tx + 16 * c]; }

    float s_dd = 0.f, s_oo = 0.f, s_do = 0.f, s_ov = 0.f;
#pragma unroll
    for (int r = 0; r < 2; r++)
#pragma unroll
        for (int c = 0; c < 4; c++) {
            float d2v = fmaf(-2.f, md[r][c], rmi[r] + rmj[c]);   // ||mi-mj||^2
            float oDv = fmaxf(fmaf(-2.f, dot[r][c], ipi[r] + ipj[c]), EPSF);
            s_dd = fmaf(d2v, d2v, s_dd);
            s_oo = fmaf(oDv, oDv, s_oo);
            s_do = fmaf(d2v, oDv, s_do);
            if ((i0 + ty + 32 * r) != (j0 + tx + 16 * c))
                s_ov += ovacc[r][c];
        }

    // ---- block reduction ----
#pragma unroll
    for (int off = 16; off > 0; off >>= 1) {
        s_dd += __shfl_xor_sync(0xffffffffu, s_dd, off);
        s_oo += __shfl_xor_sync(0xffffffffu, s_oo, off);
        s_do += __shfl_xor_sync(0xffffffffu, s_do, off);
        s_ov += __shfl_xor_sync(0xffffffffu, s_ov, off);
        exc  += __shfl_xor_sync(0xffffffffu, exc,  off);
        shp  += __shfl_xor_sync(0xffffffffu, shp,  off);
    }
    int warp = tid >> 5, lane = tid & 31;
    if (lane == 0) {
        bred[0][warp] = s_dd; bred[1][warp] = s_oo; bred[2][warp] = s_do;
        bred[3][warp] = s_ov; bred[4][warp] = exc;  bred[5][warp] = shp;
    }
    __syncthreads();
    if (tid == 0) {
        float a0 = 0.f, a1 = 0.f, a2 = 0.f, a3 = 0.f, a4 = 0.f, a5 = 0.f;
#pragma unroll
        for (int w = 0; w < 16; w++) {
            a0 += bred[0][w]; a1 += bred[1][w]; a2 += bred[2][w];
            a3 += bred[3][w]; a4 += bred[4][w]; a5 += bred[5][w];
        }
        double wgt = diag ? 1.0 : 2.0;   // symmetry: off-diagonal tiles count twice
        atomicAdd(&g_acc[0], wgt * (double)a0);
        atomicAdd(&g_acc[1], wgt * (double)a1);
        atomicAdd(&g_acc[2], wgt * (double)a2);
        atomicAdd(&g_acc[3], wgt * (double)a3);
        if (diag) {
            atomicAdd(&g_acc[4], (double)a4);
            atomicAdd(&g_acc[5], (double)a5);
        }

        __threadfence();
        unsigned prev = atomicAdd(&g_count, 1u);
        if (prev == NBLK - 1) {
            __threadfence();
            double S_dd = g_acc[0], S_oo = g_acc[1], S_do = g_acc[2];
            double a = sqrt(S_dd), b = sqrt(S_oo);
            double ac = fmax(a, 1e-5), bc = fmax(b, 1e-5);
            double q = S_dd / (ac * ac) + S_oo / (bc * bc) - 2.0 * S_do / (ac * bc);
            if (q < 0.0) q = 0.0;
            out[0] = (float)(sqrt(q) + g_acc[3] + g_acc[4] + g_acc[5]);
            // reset state for the next graph replay
            g_acc[0] = 0.0; g_acc[1] = 0.0; g_acc[2] = 0.0;
            g_acc[3] = 0.0; g_acc[4] = 0.0; g_acc[5] = 0.0;
            g_count = 0u;
        }
    }
}

// ---------------------------------------------------------------------------
extern "C" void kernel_launch(void* const* d_in, const int* in_sizes, int n_in,
                              void* d_out, int out_size) {
    const float* cl  = (const float*)d_in[0];  // childrenLower  [4096,32]
    const float* ch  = (const float*)d_in[1];  // childrenHigher [4096,32]
    const float* pL  = (const float*)d_in[2];  // parentL_ [32]
    const float* pH  = (const float*)d_in[3];  // parentH_ [32]
    const float* pR  = (const float*)d_in[4];  // parentRange [32]
    const float* lr  = (const float*)d_in[5];  // leavesRatio [4096]
    const float* om  = (const float*)d_in[6];  // omegaEmb [1024,128]
    const int*  idxs = (const int*)d_in[7];    // idIndexes [1024]
    float* out = (float*)d_out;

    const int SMEM = (6 * TILE * LHS4 + 2 * TILE * WS4) * (int)sizeof(float); // 122880 B
    cudaFuncSetAttribute(pair_kernel, cudaFuncAttributeMaxDynamicSharedMemorySize, SMEM);

    pair_kernel<<<NBLK, dim3(16, 32), SMEM>>>(cl, ch, pL, pH, pR, lr, om, idxs, out);
}